// round 8
// baseline (speedup 1.0000x reference)
#include <cuda_runtime.h>
#include <cuda_bf16.h>
#include <cstdint>

#define MAX_NODES 170000
#define IN_DIM    64
#define OUT_DIM   40
#define CSR_CAP   64     // per-node bucket capacity; deg~Poisson(7), max<<64

// Scratch (device globals — no allocation allowed in kernel_launch).
// g_cnt is zero at entry of every run: zero-initialized at module load, and
// k_aggregate re-zeroes every entry at the end of each run.
__device__ float g_hp[(size_t)MAX_NODES * OUT_DIM];   // UNNORMED feats@W^T [N,40]
__device__ float g_norm[MAX_NODES];                   // rsqrt(max(deg,1))
__device__ int   g_cnt[MAX_NODES];                    // in-degree / bucket fill count
__device__ int   g_csr[(size_t)MAX_NODES * CSR_CAP];  // bucketed CSR: src ids per dst

// ---- packed f32x2 helpers (Blackwell FFMA2 via PTX) ------------------------
__device__ __forceinline__ unsigned long long pack2(float x, float y) {
    unsigned long long r;
    asm("mov.b64 %0, {%1, %2};" : "=l"(r) : "f"(x), "f"(y));
    return r;
}
__device__ __forceinline__ void unpack2(unsigned long long v, float& x, float& y) {
    asm("mov.b64 {%0, %1}, %2;" : "=f"(x), "=f"(y) : "l"(v));
}
__device__ __forceinline__ void fma2(unsigned long long& d,
                                     unsigned long long a, unsigned long long b) {
    asm("fma.rn.f32x2 %0, %1, %2, %3;" : "=l"(d) : "l"(a), "l"(b), "l"(d));
}
__device__ __forceinline__ unsigned long long add2(unsigned long long a,
                                                   unsigned long long b) {
    unsigned long long r;
    asm("add.rn.f32x2 %0, %1, %2;" : "=l"(r) : "l"(a), "l"(b));
    return r;
}

// ---------------------------------------------------------------------------
// K1a: bucketed CSR build, 4 edges per thread.
//   pos = cnt[dst]++;  csr[dst*64 + pos] = src
// At the 4.8M-lane-atomic L2 throughput floor (~20us) -> overlapped with K2.
// ---------------------------------------------------------------------------
__global__ void k_csr(const int4* __restrict__ src4,
                      const int4* __restrict__ dst4, int E4,
                      const int* __restrict__ src,
                      const int* __restrict__ dst, int E) {
    int i = blockIdx.x * blockDim.x + threadIdx.x;
    if (i < E4) {
        int4 s = __ldg(&src4[i]);
        int4 d = __ldg(&dst4[i]);
        int p0 = atomicAdd(&g_cnt[d.x], 1);
        int p1 = atomicAdd(&g_cnt[d.y], 1);
        int p2 = atomicAdd(&g_cnt[d.z], 1);
        int p3 = atomicAdd(&g_cnt[d.w], 1);
        if (p0 < CSR_CAP) g_csr[(size_t)d.x * CSR_CAP + p0] = s.x;
        if (p1 < CSR_CAP) g_csr[(size_t)d.y * CSR_CAP + p1] = s.y;
        if (p2 < CSR_CAP) g_csr[(size_t)d.z * CSR_CAP + p2] = s.z;
        if (p3 < CSR_CAP) g_csr[(size_t)d.w * CSR_CAP + p3] = s.w;
    }
    int t = E4 * 4 + i;
    if (i < 4 && t < E) {
        int s = src[t], d = dst[t];
        int pos = atomicAdd(&g_cnt[d], 1);
        if (pos < CSR_CAP) g_csr[(size_t)d * CSR_CAP + pos] = s;
    }
}

// K1b: norms from counts (tiny)
__global__ void k_norm(int N) {
    int i = blockIdx.x * blockDim.x + threadIdx.x;
    if (i < N) g_norm[i] = rsqrtf(fmaxf((float)g_cnt[i], 1.0f));
}

// ---------------------------------------------------------------------------
// K2: hp_un[n,c] = dot(feats[n,:], W[c,:])  (no norm -> independent of K1,
// runs on a forked stream concurrently with k_csr).
// 320 threads = 40 cols x 8 pair-groups; 32 nodes/block.
// fs2[p][d] = {feat[p][d], feat[p+16][d]}, stride 66 (16B aligned) -> pair
// loads are LDS.128, broadcast across the 40 lanes sharing gp.
// W2 stride 68 -> float4 loads conflict-free (bank step 4 per lane).
// 80 LDS + 128 FMA2 per thread (was 160 LDS).
// ---------------------------------------------------------------------------
__global__ __launch_bounds__(320)
void k_project(const float* __restrict__ feats,
               const float* __restrict__ W, int N) {
    __shared__ float  W2[OUT_DIM * 68];
    __shared__ float2 fs2[16 * 66];

    const int tid = threadIdx.x;             // 0..319
    const int node0 = blockIdx.x * 32;

    for (int i = tid; i < OUT_DIM * IN_DIM; i += 320) {
        int c = i >> 6, d = i & 63;
        W2[c * 68 + d] = W[i];
    }
    int nrows = N - node0; if (nrows > 32) nrows = 32;
    for (int i = tid; i < nrows * IN_DIM; i += 320) {
        int r = i >> 6, d = i & 63;
        int p = r & 15, half = r >> 4;
        reinterpret_cast<float*>(&fs2[p * 66 + d])[half] =
            feats[(size_t)(node0 + r) * IN_DIM + d];
    }
    __syncthreads();

    const int c  = tid % OUT_DIM;            // column 0..39
    const int gp = tid / OUT_DIM;            // pair group 0..7
    // two chains per output pair to cover FMA2 latency
    unsigned long long aa0 = pack2(0.f, 0.f), aa1 = pack2(0.f, 0.f); // (gp, gp+16)
    unsigned long long ab0 = pack2(0.f, 0.f), ab1 = pack2(0.f, 0.f); // (gp+8, gp+24)

    const ulonglong2* __restrict__ fa_base =
        reinterpret_cast<const ulonglong2*>(&fs2[gp * 66]);
    const ulonglong2* __restrict__ fb_base =
        reinterpret_cast<const ulonglong2*>(&fs2[(gp + 8) * 66]);

#pragma unroll
    for (int d = 0; d < IN_DIM; d += 4) {
        float4 w = *reinterpret_cast<const float4*>(&W2[c * 68 + d]);
        unsigned long long wp0 = pack2(w.x, w.x);
        unsigned long long wp1 = pack2(w.y, w.y);
        unsigned long long wp2 = pack2(w.z, w.z);
        unsigned long long wp3 = pack2(w.w, w.w);
        ulonglong2 fa01 = fa_base[(d >> 1) + 0];   // pairs d, d+1
        ulonglong2 fa23 = fa_base[(d >> 1) + 1];   // pairs d+2, d+3
        ulonglong2 fb01 = fb_base[(d >> 1) + 0];
        ulonglong2 fb23 = fb_base[(d >> 1) + 1];
        fma2(aa0, fa01.x, wp0);
        fma2(ab0, fb01.x, wp0);
        fma2(aa1, fa01.y, wp1);
        fma2(ab1, fb01.y, wp1);
        fma2(aa0, fa23.x, wp2);
        fma2(ab0, fb23.x, wp2);
        fma2(aa1, fa23.y, wp3);
        fma2(ab1, fb23.y, wp3);
    }
    unsigned long long acc_a = add2(aa0, aa1);
    unsigned long long acc_b = add2(ab0, ab1);

    float a_lo, a_hi, b_lo, b_hi;
    unpack2(acc_a, a_lo, a_hi);
    unpack2(acc_b, b_lo, b_hi);
    const int n0 = node0 + gp;
    if (n0      < N) g_hp[(size_t)(n0     ) * OUT_DIM + c] = a_lo;
    if (n0 +  8 < N) g_hp[(size_t)(n0 +  8) * OUT_DIM + c] = b_lo;
    if (n0 + 16 < N) g_hp[(size_t)(n0 + 16) * OUT_DIM + c] = a_hi;
    if (n0 + 24 < N) g_hp[(size_t)(n0 + 24) * OUT_DIM + c] = b_hi;
}

// ---------------------------------------------------------------------------
// K3: gather-aggregate. 5 lanes per dst row; lane k owns float4 chunks k, k+5.
//   out[d,:] = norm[d] * sum_i norm[s_i] * hp_un[s_i,:] + b
// Unroll x4 with int4 CSR loads. Lane 0 re-zeroes cnt[d] for the next replay.
// ---------------------------------------------------------------------------
__global__ __launch_bounds__(640)
void k_aggregate(float* __restrict__ out, const float4* __restrict__ b4, int N) {
    const int gt = blockIdx.x * 640 + threadIdx.x;
    const int d  = gt / 5;
    const int k  = gt - d * 5;           // 0..4
    if (d >= N) return;

    int cnt = g_cnt[d];
    const float nm = g_norm[d];
    int m = cnt < CSR_CAP ? cnt : CSR_CAP;
    const int4* __restrict__ row4 =
        reinterpret_cast<const int4*>(g_csr + (size_t)d * CSR_CAP);
    const float4* __restrict__ hp4 = reinterpret_cast<const float4*>(g_hp);

    float4 a0 = make_float4(0.f, 0.f, 0.f, 0.f);
    float4 a1 = make_float4(0.f, 0.f, 0.f, 0.f);

    int i = 0;
    for (; i + 4 <= m; i += 4) {
        int4 s = __ldg(&row4[i >> 2]);
        float n0 = __ldg(&g_norm[s.x]);
        float n1 = __ldg(&g_norm[s.y]);
        float n2 = __ldg(&g_norm[s.z]);
        float n3 = __ldg(&g_norm[s.w]);
        float4 u0 = hp4[(size_t)s.x * 10 + k];
        float4 u1 = hp4[(size_t)s.x * 10 + k + 5];
        float4 v0 = hp4[(size_t)s.y * 10 + k];
        float4 v1 = hp4[(size_t)s.y * 10 + k + 5];
        float4 w0 = hp4[(size_t)s.z * 10 + k];
        float4 w1 = hp4[(size_t)s.z * 10 + k + 5];
        float4 x0 = hp4[(size_t)s.w * 10 + k];
        float4 x1 = hp4[(size_t)s.w * 10 + k + 5];
        a0.x += u0.x * n0 + v0.x * n1; a0.y += u0.y * n0 + v0.y * n1;
        a0.z += u0.z * n0 + v0.z * n1; a0.w += u0.w * n0 + v0.w * n1;
        a1.x += u1.x * n0 + v1.x * n1; a1.y += u1.y * n0 + v1.y * n1;
        a1.z += u1.z * n0 + v1.z * n1; a1.w += u1.w * n0 + v1.w * n1;
        a0.x += w0.x * n2 + x0.x * n3; a0.y += w0.y * n2 + x0.y * n3;
        a0.z += w0.z * n2 + x0.z * n3; a0.w += w0.w * n2 + x0.w * n3;
        a1.x += w1.x * n2 + x1.x * n3; a1.y += w1.y * n2 + x1.y * n3;
        a1.z += w1.z * n2 + x1.z * n3; a1.w += w1.w * n2 + x1.w * n3;
    }
    const int* __restrict__ row = reinterpret_cast<const int*>(row4);
    for (; i < m; i++) {
        int s0 = __ldg(&row[i]);
        float n0 = __ldg(&g_norm[s0]);
        float4 u0 = hp4[(size_t)s0 * 10 + k];
        float4 u1 = hp4[(size_t)s0 * 10 + k + 5];
        a0.x += u0.x * n0; a0.y += u0.y * n0; a0.z += u0.z * n0; a0.w += u0.w * n0;
        a1.x += u1.x * n0; a1.y += u1.y * n0; a1.z += u1.z * n0; a1.w += u1.w * n0;
    }

    float4 bb0 = __ldg(&b4[k]);
    float4 bb1 = __ldg(&b4[k + 5]);
    float4 o0, o1;
    o0.x = a0.x * nm + bb0.x; o0.y = a0.y * nm + bb0.y;
    o0.z = a0.z * nm + bb0.z; o0.w = a0.w * nm + bb0.w;
    o1.x = a1.x * nm + bb1.x; o1.y = a1.y * nm + bb1.y;
    o1.z = a1.z * nm + bb1.z; o1.w = a1.w * nm + bb1.w;

    float4* op = reinterpret_cast<float4*>(out + (size_t)d * OUT_DIM);
    op[k] = o0;
    op[k + 5] = o1;

    if (k == 0) g_cnt[d] = 0;            // reset for next replay
}

// ---------------------------------------------------------------------------
extern "C" void kernel_launch(void* const* d_in, const int* in_sizes, int n_in,
                              void* d_out, int out_size) {
    const float* feats = (const float*)d_in[0];
    const float* W     = (const float*)d_in[1];
    const float* b     = (const float*)d_in[2];
    const int*   src   = (const int*)d_in[3];   // JAX x64 disabled -> int32
    const int*   dst   = (const int*)d_in[4];
    float* out = (float*)d_out;

    const int OUT = in_sizes[2];            // 40
    const int IN  = in_sizes[1] / OUT;      // 64
    const int N   = in_sizes[0] / IN;       // 170000
    const int E   = in_sizes[3];            // 1200000
    (void)n_in; (void)OUT; (void)out_size;

    // One-time host resources (streams/events are host objects; no device
    // memory is allocated). Work per call is identical and deterministic.
    static cudaStream_t s2 = [] {
        cudaStream_t s; cudaStreamCreateWithFlags(&s, cudaStreamNonBlocking);
        return s;
    }();
    static cudaEvent_t ev_fork = [] {
        cudaEvent_t e; cudaEventCreateWithFlags(&e, cudaEventDisableTiming);
        return e;
    }();
    static cudaEvent_t ev_join = [] {
        cudaEvent_t e; cudaEventCreateWithFlags(&e, cudaEventDisableTiming);
        return e;
    }();

    // Fork: k_project (independent of g_cnt) runs concurrently with k_csr.
    cudaEventRecord(ev_fork, 0);
    cudaStreamWaitEvent(s2, ev_fork, 0);
    k_project<<<(N + 31) / 32, 320, 0, s2>>>(feats, W, N);
    cudaEventRecord(ev_join, s2);

    // Main stream: CSR build + norms.
    {
        int E4 = E / 4;
        int blocks = (E4 + 255) / 256;
        k_csr<<<blocks, 256>>>((const int4*)src, (const int4*)dst, E4,
                               src, dst, E);
    }
    k_norm<<<(N + 255) / 256, 256>>>(N);

    // Join, then aggregate.
    cudaStreamWaitEvent(0, ev_join, 0);
    {
        long long total = (long long)N * 5;
        int blocks = (int)((total + 639) / 640);
        k_aggregate<<<blocks, 640>>>(out, (const float4*)b, N);
    }
}